// round 14
// baseline (speedup 1.0000x reference)
#include <cuda_runtime.h>
#include <cuda_fp16.h>
#include <cstdint>

// Problem constants
#define BATCH   4
#define SEQ     6144
#define DIM     384
#define FCHUNK  3
#define NB      12      // BATCH*FCHUNK
#define LEN     2048    // SEQ/FCHUNK
#define DIN     192     // DIM/2
#define DSTATE  16
#define DTRANK  24
#define MTOT    (NB*LEN)    // 24576

// ---------------------------------------------------------------------------
// Scratch (static __device__ arrays; no allocation allowed)
// ---------------------------------------------------------------------------
__device__ float  g_xp[MTOT * DIM];           // in_proj output (fp32)
__device__ float  g_xc[NB * DIN * LEN];       // (b,d,l) conv+silu output
__device__ float  g_dt[NB * DTRANK * LEN];    // (b,r,l)
__device__ float  g_Bm[NB * LEN * DSTATE];    // (b,l,n)
__device__ float  g_Cm[NB * LEN * DSTATE];    // (b,l,n)
__device__ float  g_delta[NB * DIN * LEN];    // (b,d,l)
__device__ float  g_yf[NB * DIN * LEN];       // fwd scan out (b,d,l)
__device__ float  g_yb[NB * DIN * LEN];       // bwd scan out (b,d,l)
__device__ __half g_xh[MTOT * DIM];           // fp16 x
__device__ __half g_Ah[MTOT * DIM];           // fp16 [ysum | xc], row-major
__device__ __half g_wih[DIM * DIM];           // fp16 in_proj_w
__device__ __half g_woh[DIM * DIM];           // fp16 out_proj_w

// ---------------------------------------------------------------------------
// helpers
// ---------------------------------------------------------------------------
__device__ __forceinline__ uint32_t smem_u32(const void* p) {
    uint32_t a;
    asm("{ .reg .u64 t; cvta.to.shared.u64 t, %1; cvt.u32.u64 %0, t; }"
        : "=r"(a) : "l"(p));
    return a;
}
__device__ __forceinline__ void cp16(uint32_t dst, const void* src) {
    asm volatile("cp.async.ca.shared.global [%0], [%1], 16;"
                 :: "r"(dst), "l"(src) : "memory");
}
#define CP_COMMIT() asm volatile("cp.async.commit_group;" ::: "memory")
#define CP_WAIT1()  asm volatile("cp.async.wait_group 1;" ::: "memory")
#define CP_WAIT0()  asm volatile("cp.async.wait_group 0;" ::: "memory")

__device__ __forceinline__ void mma_f16(float* c, const uint32_t* a,
                                        const uint32_t* b) {
    asm volatile(
        "mma.sync.aligned.m16n8k16.row.col.f32.f16.f16.f32 "
        "{%0,%1,%2,%3}, {%4,%5,%6,%7}, {%8,%9}, {%0,%1,%2,%3};"
        : "+f"(c[0]), "+f"(c[1]), "+f"(c[2]), "+f"(c[3])
        : "r"(a[0]), "r"(a[1]), "r"(a[2]), "r"(a[3]), "r"(b[0]), "r"(b[1]));
}

// ---------------------------------------------------------------------------
// cvt_half: fp32 -> fp16, float4-granular grid-stride
// ---------------------------------------------------------------------------
__global__ __launch_bounds__(256)
void cvt_half(const float* __restrict__ src, __half* __restrict__ dst, int n4)
{
    for (int i = blockIdx.x * blockDim.x + threadIdx.x; i < n4;
         i += gridDim.x * blockDim.x) {
        float4 v = ((const float4*)src)[i];
        __half2 h0 = __floats2half2_rn(v.x, v.y);
        __half2 h1 = __floats2half2_rn(v.z, v.w);
        ((__half2*)dst)[2 * i]     = h0;
        ((__half2*)dst)[2 * i + 1] = h1;
    }
}

// ---------------------------------------------------------------------------
// fp16 HMMA GEMM (unified): C[M,384] = A[M,384] @ W[384,384]^T + bias
// A, W row-major fp16 (pre-converted). 128x128 tile, BK=32 (2 ksteps of 16),
// 8 warps (4 M x 2 N), warp tile 32x64, 3-stage cp.async, 61.4KB smem,
// 2 CTAs/SM.
// ---------------------------------------------------------------------------
#define HS      40
#define TILE_H  (128 * HS)            // 5120 halves per array per stage
#define GEMM_SMEM_H (6 * TILE_H * 2)  // 61440 B

__global__ __launch_bounds__(256, 2)
void gemm_h_kernel(const __half* __restrict__ A,
                   const __half* __restrict__ W,
                   const float* __restrict__ bias,
                   float* __restrict__ C)
{
    extern __shared__ __half smh[];
    __half* AsBuf = smh;                   // 3 stages
    __half* BsBuf = smh + 3 * TILE_H;      // 3 stages

    const int tid  = threadIdx.x;
    const int wid  = tid >> 5;
    const int lane = tid & 31;
    const int g = lane >> 2;
    const int t = lane & 3;
    const int wm = wid >> 1;
    const int wn = wid & 1;

    const int m0 = blockIdx.y * 128;
    const int n0 = blockIdx.x * 128;

    const uint32_t sAu = smem_u32(AsBuf);
    const uint32_t sBu = smem_u32(BsBuf);

    float acc[2][8][4];
#pragma unroll
    for (int mt = 0; mt < 2; mt++)
#pragma unroll
        for (int nt = 0; nt < 8; nt++)
#pragma unroll
            for (int q = 0; q < 4; q++) acc[mt][nt][q] = 0.f;

    auto load_tile = [&](int kt, int buf) {
        const int k0 = kt * 32;
#pragma unroll
        for (int it = 0; it < 2; it++) {
            int idx = it * 256 + tid;
            int r = idx >> 2, c = idx & 3;
            cp16(sBu + (uint32_t)(buf * TILE_H + r * HS + c * 8) * 2,
                 &W[(size_t)(n0 + r) * DIM + k0 + c * 8]);
        }
#pragma unroll
        for (int it = 0; it < 2; it++) {
            int idx = it * 256 + tid;
            int r = idx >> 2, c = idx & 3;
            cp16(sAu + (uint32_t)(buf * TILE_H + r * HS + c * 8) * 2,
                 &A[(size_t)(m0 + r) * DIM + k0 + c * 8]);
        }
        CP_COMMIT();
    };

    load_tile(0, 0);
    load_tile(1, 1);

    for (int kt = 0; kt < 12; kt++) {
        CP_WAIT1();
        __syncthreads();

        if (kt + 2 < 12) load_tile(kt + 2, (kt + 2) % 3);
        else CP_COMMIT();   // uniform group bookkeeping

        const int buf = kt % 3;
        const __half* As = AsBuf + buf * TILE_H;
        const __half* Bs = BsBuf + buf * TILE_H;

#pragma unroll
        for (int s = 0; s < 2; s++) {
            const int kb = s * 16;
            uint32_t bf[8][2];
#pragma unroll
            for (int nt = 0; nt < 8; nt++) {
                int n = wn * 64 + nt * 8 + g;
                bf[nt][0] = *(const uint32_t*)&Bs[n * HS + kb + 2 * t];
                bf[nt][1] = *(const uint32_t*)&Bs[n * HS + kb + 2 * t + 8];
            }
#pragma unroll
            for (int mt = 0; mt < 2; mt++) {
                int row = wm * 32 + mt * 16 + g;
                uint32_t af[4];
                af[0] = *(const uint32_t*)&As[row * HS + kb + 2 * t];
                af[1] = *(const uint32_t*)&As[(row + 8) * HS + kb + 2 * t];
                af[2] = *(const uint32_t*)&As[row * HS + kb + 2 * t + 8];
                af[3] = *(const uint32_t*)&As[(row + 8) * HS + kb + 2 * t + 8];
#pragma unroll
                for (int nt = 0; nt < 8; nt++)
                    mma_f16(acc[mt][nt], af, bf[nt]);
            }
        }
        __syncthreads();
    }

#pragma unroll
    for (int mt = 0; mt < 2; mt++) {
        int row = m0 + wm * 32 + mt * 16 + g;
#pragma unroll
        for (int nt = 0; nt < 8; nt++) {
            int col = n0 + wn * 64 + nt * 8 + t * 2;
            float b0 = bias[col], b1 = bias[col + 1];
            float2 v0 = make_float2(acc[mt][nt][0] + b0, acc[mt][nt][1] + b1);
            float2 v1 = make_float2(acc[mt][nt][2] + b0, acc[mt][nt][3] + b1);
            *(float2*)&C[(size_t)row * DIM + col] = v0;
            *(float2*)&C[(size_t)(row + 8) * DIM + col] = v1;
        }
    }
}

// ---------------------------------------------------------------------------
// Grouped conv (k=3, SAME, groups=192, 2 in-ch per group) + SiLU  (R13 exact)
// ---------------------------------------------------------------------------
__global__ __launch_bounds__(1024)
void conv_silu_kernel(const float* __restrict__ conv_w,
                      const float* __restrict__ conv_b)
{
    __shared__ float s[34][65];
    const int b  = blockIdx.z;
    const int d0 = blockIdx.y * 32;
    const int l0 = blockIdx.x * 32;
    const int tid = threadIdx.y * 32 + threadIdx.x;

    for (int e = tid; e < 34 * 64; e += 1024) {
        int li = e >> 6;
        int ci = e & 63;
        int l = l0 - 1 + li;
        float v = 0.f;
        if (l >= 0 && l < LEN)
            v = g_xp[(b * LEN + l) * DIM + 2 * d0 + ci];
        s[li][ci] = v;
    }
    __syncthreads();

    const int tx = threadIdx.x, ty = threadIdx.y;
    const int d = d0 + ty;
    float acc = conv_b[d];
    const float* w = conv_w + d * 6;
#pragma unroll
    for (int i = 0; i < 2; i++)
#pragma unroll
        for (int j = 0; j < 3; j++)
            acc = fmaf(s[tx + j][2 * ty + i], w[i * 3 + j], acc);
    float y = acc / (1.f + __expf(-acc));
    g_xc[(b * DIN + d) * LEN + l0 + tx] = y;
}

// ---------------------------------------------------------------------------
// x_proj (R13 exact)
// ---------------------------------------------------------------------------
__global__ __launch_bounds__(128)
void xproj_kernel(const float* __restrict__ x_proj_w)
{
    __shared__ float sW[14 * DIN];
    const int b = blockIdx.y;
    const int l = blockIdx.x * 128 + threadIdx.x;
    const int r0 = blockIdx.z * 14;

    for (int i = threadIdx.x; i < 14 * DIN; i += 128)
        sW[i] = x_proj_w[r0 * DIN + i];
    __syncthreads();

    float acc[14];
#pragma unroll
    for (int j = 0; j < 14; j++) acc[j] = 0.f;

    for (int d = 0; d < DIN; d++) {
        float v = g_xc[(b * DIN + d) * LEN + l];
#pragma unroll
        for (int j = 0; j < 14; j++)
            acc[j] = fmaf(sW[j * DIN + d], v, acc[j]);
    }
#pragma unroll
    for (int j = 0; j < 14; j++) {
        int r = r0 + j;
        if (r < DTRANK)
            g_dt[(b * DTRANK + r) * LEN + l] = acc[j];
        else if (r < DTRANK + DSTATE)
            g_Bm[(b * LEN + l) * DSTATE + (r - DTRANK)] = acc[j];
        else
            g_Cm[(b * LEN + l) * DSTATE + (r - DTRANK - DSTATE)] = acc[j];
    }
}

// ---------------------------------------------------------------------------
// delta (R13 exact)
// ---------------------------------------------------------------------------
__global__ __launch_bounds__(128)
void delta_kernel(const float* __restrict__ dt_proj_w,
                  const float* __restrict__ dt_proj_b)
{
    __shared__ float sW[24 * DTRANK];
    const int b = blockIdx.y;
    const int l = blockIdx.x * 128 + threadIdx.x;
    const int d0 = blockIdx.z * 24;

    for (int i = threadIdx.x; i < 24 * DTRANK; i += 128)
        sW[i] = dt_proj_w[d0 * DTRANK + i];
    __syncthreads();

    float dt[DTRANK];
#pragma unroll
    for (int r = 0; r < DTRANK; r++)
        dt[r] = g_dt[(b * DTRANK + r) * LEN + l];

#pragma unroll 4
    for (int j = 0; j < 24; j++) {
        int d = d0 + j;
        float a = dt_proj_b[d];
#pragma unroll
        for (int r = 0; r < DTRANK; r++)
            a = fmaf(sW[j * DTRANK + r], dt[r], a);
        float sp = (a > 20.f) ? a : log1pf(__expf(a));
        g_delta[(b * DIN + d) * LEN + l] = sp;
    }
}

// ---------------------------------------------------------------------------
// Bidirectional selective scan v2.3 (R13 exact — smem-transpose reduction)
// ---------------------------------------------------------------------------
#define SCHUNK   64
#define SC_BUF   6272
#define SC_DU    4096
#define PB_D     272
#define PB_DIR   (8 * PB_D)
#define SC_SMEM  ((2 * SC_BUF + 2 * PB_DIR) * 4)   // 67584 B

__global__ __launch_bounds__(256)
void scan_kernel(const float* __restrict__ A_log,
                 const float* __restrict__ Ab_log)
{
    extern __shared__ float ss[];
    float* pbuf = ss + 2 * SC_BUF;
    const int b  = blockIdx.x / (DIN / 8);
    const int d0 = (blockIdx.x % (DIN / 8)) * 8;
    const int tid = threadIdx.x;
    const int wid = tid >> 5, lane = tid & 31;
    const bool bwd = wid >= 4;
    const int w = bwd ? wid - 4 : wid;
    const int half = lane >> 4, n = lane & 15;
    const int dloc = 2 * w + half;
    const int dg = d0 + dloc;

    const float Aval = -__expf(bwd ? Ab_log[dg * DSTATE + n]
                                   : A_log[dg * DSTATE + n]);
    float* pst = pbuf + (bwd ? PB_DIR : 0) + dloc * PB_D + n * 17;

    const int rdir = tid >> 7;
    const int rrem = tid & 127;
    const int rd   = rrem >> 4;
    const int rt   = rrem & 15;
    const float* rq = pbuf + rdir * PB_DIR + rd * PB_D + rt;
    float* ybase = (rdir ? g_yb : g_yf) + (size_t)(b * DIN + d0 + rd) * LEN;

    const uint32_t sbase = smem_u32(ss);

    auto load_chunk = [&](int c, int buf) {
        const uint32_t dstb = sbase + (uint32_t)buf * SC_BUF * 4;
        const int lf = c * SCHUNK;
        const int lb = LEN - (c + 1) * SCHUNK;
#pragma unroll
        for (int it = 0; it < 4; it++) {
            int task = it * 256 + tid;
            int arr = task >> 8, r = task & 255;
            int lo = r >> 2, n4 = (r & 3) * 4;
            int ls = (arr < 2) ? lf + lo : lb + lo;
            const float* src = ((arr & 1) ? g_Cm : g_Bm)
                + ((size_t)(b * LEN + ls) * DSTATE + n4);
            cp16(dstb + (uint32_t)(arr * 1024 + lo * 16 + n4) * 4, src);
        }
#pragma unroll
        for (int it = 0; it < 2; it++) {
            int q = it * 256 + tid;
            int arr = q >> 7, s = q & 127;
            int dl = s >> 4, l4 = (s & 15) * 4;
            int ls = (arr < 2) ? lf + l4 : lb + l4;
            const float* src = ((arr & 1) ? g_xc : g_delta)
                + ((size_t)(b * DIN + d0 + dl) * LEN + ls);
            cp16(dstb + (uint32_t)(SC_DU + arr * 544 + dl * 68 + l4) * 4, src);
        }
    };

    float h = 0.f;
    load_chunk(0, 0);
    CP_COMMIT();

    for (int c = 0; c < LEN / SCHUNK; c++) {
        const int buf = c & 1;
        if (c + 1 < LEN / SCHUNK) load_chunk(c + 1, buf ^ 1);
        CP_COMMIT();
        CP_WAIT1();
        __syncthreads();

        const float* sm   = ss + buf * SC_BUF;
        const float* sB   = sm + (bwd ? 2048 : 0);
        const float* sC   = sB + 1024;
        const float* sdel = sm + SC_DU + (bwd ? 1088 : 0) + dloc * 68;
        const float* su   = sdel + 544;

#pragma unroll
        for (int w2 = 0; w2 < 4; w2++) {
            if (!bwd) {
#pragma unroll
                for (int j = 0; j < 4; j++) {
                    const int t0 = (w2 * 4 + j) * 4;
#pragma unroll
                    for (int k = 0; k < 4; k++) {
                        int t = t0 + k;
                        float del = sdel[t], u = su[t];
                        float Bv = sB[t * 16 + n], Cv = sC[t * 16 + n];
                        float dA = __expf(del * Aval);
                        h = fmaf(dA, h, del * u * Bv);
                        pst[j * 4 + k] = h * Cv;
                    }
                }
            } else {
#pragma unroll
                for (int j = 0; j < 4; j++) {
                    const int t0 = (15 - (w2 * 4 + j)) * 4;
#pragma unroll
                    for (int k = 0; k < 4; k++) {
                        int t = t0 + 3 - k;
                        float del = sdel[t], u = su[t];
                        float Bv = sB[t * 16 + n], Cv = sC[t * 16 + n];
                        float dA = __expf(del * Aval);
                        h = fmaf(dA, h, del * u * Bv);
                        pst[(3 - j) * 4 + (3 - k)] = h * Cv;
                    }
                }
            }
            __syncthreads();
            {
                float s0 = 0.f, s1 = 0.f;
#pragma unroll
                for (int nn = 0; nn < 16; nn += 2) {
                    s0 += rq[nn * 17];
                    s1 += rq[(nn + 1) * 17];
                }
                int l = (rdir == 0)
                    ? (c * SCHUNK + w2 * 16 + rt)
                    : (LEN - (c + 1) * SCHUNK + (3 - w2) * 16 + rt);
                ybase[l] = s0 + s1;
            }
            __syncthreads();
        }
    }
}

// ---------------------------------------------------------------------------
// fuse_T (R13 exact): transpose + add + fp16 pack -> g_Ah [m][384]
// ---------------------------------------------------------------------------
__global__ __launch_bounds__(1024)
void fuse_T_kernel(const float* __restrict__ Dv)
{
    __shared__ float sy[32][33];
    __shared__ float sz[32][33];
    const int b  = blockIdx.z;
    const int d0 = blockIdx.y * 32;
    const int l0 = blockIdx.x * 32;
    const int tx = threadIdx.x, ty = threadIdx.y;

    const int d = d0 + ty;
    const size_t off = (size_t)(b * DIN + d) * LEN + l0 + tx;
    float yf = g_yf[off];
    float yb = g_yb[off];
    float xc = g_xc[off];
    sy[ty][tx] = yf + yb + 2.f * Dv[d] * xc;
    sz[ty][tx] = xc;
    __syncthreads();

    __half* dst = g_Ah + (size_t)(b * LEN + l0 + ty) * DIM;
    dst[d0 + tx]       = __float2half_rn(sy[tx][ty]);
    dst[DIN + d0 + tx] = __float2half_rn(sz[tx][ty]);
}

// ---------------------------------------------------------------------------
// Launch
// ---------------------------------------------------------------------------
extern "C" void kernel_launch(void* const* d_in, const int* in_sizes, int n_in,
                              void* d_out, int out_size)
{
    (void)in_sizes; (void)n_in; (void)out_size;
    const float* x          = (const float*)d_in[0];
    const float* in_proj_w  = (const float*)d_in[1];
    const float* in_proj_b  = (const float*)d_in[2];
    const float* conv_w     = (const float*)d_in[3];
    const float* conv_b     = (const float*)d_in[4];
    const float* A_log      = (const float*)d_in[5];
    const float* Ab_log     = (const float*)d_in[6];
    const float* Dv         = (const float*)d_in[7];
    const float* x_proj_w   = (const float*)d_in[8];
    const float* dt_proj_w  = (const float*)d_in[9];
    const float* dt_proj_b  = (const float*)d_in[10];
    const float* out_proj_w = (const float*)d_in[11];
    const float* out_proj_b = (const float*)d_in[12];
    float* out = (float*)d_out;

    float* xp_ptr;
    __half *xh_ptr, *ah_ptr, *wih_ptr, *woh_ptr;
    cudaGetSymbolAddress((void**)&xp_ptr, g_xp);
    cudaGetSymbolAddress((void**)&xh_ptr, g_xh);
    cudaGetSymbolAddress((void**)&ah_ptr, g_Ah);
    cudaGetSymbolAddress((void**)&wih_ptr, g_wih);
    cudaGetSymbolAddress((void**)&woh_ptr, g_woh);

    cudaFuncSetAttribute(gemm_h_kernel,
                         cudaFuncAttributeMaxDynamicSharedMemorySize, GEMM_SMEM_H);
    cudaFuncSetAttribute(scan_kernel,
                         cudaFuncAttributeMaxDynamicSharedMemorySize, SC_SMEM);

    // 1-3. fp16 pre-conversion
    cvt_half<<<144, 256>>>(in_proj_w, wih_ptr, DIM * DIM / 4);
    cvt_half<<<144, 256>>>(out_proj_w, woh_ptr, DIM * DIM / 4);
    cvt_half<<<1024, 256>>>(x, xh_ptr, MTOT * DIM / 4);

    // 4. in_proj GEMM (fp16 HMMA, 3-stage, 2 CTA/SM)  [profiled slot]
    gemm_h_kernel<<<dim3(DIM / 128, MTOT / 128), 256, GEMM_SMEM_H>>>(
        xh_ptr, wih_ptr, in_proj_b, xp_ptr);

    // 5. conv + silu -> g_xc
    conv_silu_kernel<<<dim3(LEN / 32, DIN / 32, NB), dim3(32, 32)>>>(
        conv_w, conv_b);

    // 6. x_proj split -> g_dt, g_Bm, g_Cm
    xproj_kernel<<<dim3(LEN / 128, NB, 4), 128>>>(x_proj_w);

    // 7. delta = softplus(dt_proj) -> g_delta
    delta_kernel<<<dim3(LEN / 128, NB, 8), 128>>>(dt_proj_w, dt_proj_b);

    // 8. bidirectional scan v2.3 -> g_yf, g_yb
    scan_kernel<<<NB * (DIN / 8), 256, SC_SMEM>>>(A_log, Ab_log);

    // 9. fuse + transpose -> g_Ah (fp16 [m][384])
    fuse_T_kernel<<<dim3(LEN / 32, DIN / 32, NB), dim3(32, 32)>>>(Dv);

    // 10. out_proj GEMM (fp16 HMMA, 3-stage) -> d_out
    gemm_h_kernel<<<dim3(DIM / 128, MTOT / 128), 256, GEMM_SMEM_H>>>(
        ah_ptr, woh_ptr, out_proj_b, out);
}

// round 15
// speedup vs baseline: 1.0253x; 1.0253x over previous
#include <cuda_runtime.h>
#include <cuda_fp16.h>
#include <cstdint>

// Problem constants
#define BATCH   4
#define SEQ     6144
#define DIM     384
#define FCHUNK  3
#define NB      12      // BATCH*FCHUNK
#define LEN     2048    // SEQ/FCHUNK
#define DIN     192     // DIM/2
#define DSTATE  16
#define DTRANK  24
#define MTOT    (NB*LEN)    // 24576

// ---------------------------------------------------------------------------
// Scratch (static __device__ arrays; no allocation allowed)
// ---------------------------------------------------------------------------
__device__ float  g_xp[MTOT * DIM];           // in_proj output (fp32)
__device__ float  g_xc[NB * DIN * LEN];       // (b,d,l) conv+silu output
__device__ float  g_dt[NB * DTRANK * LEN];    // (b,r,l)
__device__ float  g_Bm[NB * LEN * DSTATE];    // (b,l,n)
__device__ float  g_Cm[NB * LEN * DSTATE];    // (b,l,n)
__device__ float  g_delta[NB * DIN * LEN];    // (b,d,l)
__device__ float  g_yf[NB * DIN * LEN];       // fwd scan out (b,d,l)
__device__ float  g_yb[NB * DIN * LEN];       // bwd scan out (b,d,l)
__device__ __half g_xh[MTOT * DIM];           // fp16 x
__device__ __half g_Ah[MTOT * DIM];           // fp16 [ysum | xc], row-major
__device__ __half g_wih[DIM * DIM];           // fp16 in_proj_w
__device__ __half g_woh[DIM * DIM];           // fp16 out_proj_w

// ---------------------------------------------------------------------------
// helpers
// ---------------------------------------------------------------------------
__device__ __forceinline__ uint32_t smem_u32(const void* p) {
    uint32_t a;
    asm("{ .reg .u64 t; cvta.to.shared.u64 t, %1; cvt.u32.u64 %0, t; }"
        : "=r"(a) : "l"(p));
    return a;
}
__device__ __forceinline__ void cp16(uint32_t dst, const void* src) {
    asm volatile("cp.async.ca.shared.global [%0], [%1], 16;"
                 :: "r"(dst), "l"(src) : "memory");
}
#define CP_COMMIT() asm volatile("cp.async.commit_group;" ::: "memory")
#define CP_WAIT1()  asm volatile("cp.async.wait_group 1;" ::: "memory")
#define CP_WAIT0()  asm volatile("cp.async.wait_group 0;" ::: "memory")

__device__ __forceinline__ void mma_f16(float* c, const uint32_t* a,
                                        const uint32_t* b) {
    asm volatile(
        "mma.sync.aligned.m16n8k16.row.col.f32.f16.f16.f32 "
        "{%0,%1,%2,%3}, {%4,%5,%6,%7}, {%8,%9}, {%0,%1,%2,%3};"
        : "+f"(c[0]), "+f"(c[1]), "+f"(c[2]), "+f"(c[3])
        : "r"(a[0]), "r"(a[1]), "r"(a[2]), "r"(a[3]), "r"(b[0]), "r"(b[1]));
}
__device__ __forceinline__ void ldsm_x4(uint32_t& r0, uint32_t& r1,
                                        uint32_t& r2, uint32_t& r3,
                                        uint32_t addr) {
    asm volatile("ldmatrix.sync.aligned.m8n8.x4.shared.b16 {%0,%1,%2,%3}, [%4];"
                 : "=r"(r0), "=r"(r1), "=r"(r2), "=r"(r3) : "r"(addr));
}

// ---------------------------------------------------------------------------
// cvt_half: fp32 -> fp16, float4-granular grid-stride
// ---------------------------------------------------------------------------
__global__ __launch_bounds__(256)
void cvt_half(const float* __restrict__ src, __half* __restrict__ dst, int n4)
{
    for (int i = blockIdx.x * blockDim.x + threadIdx.x; i < n4;
         i += gridDim.x * blockDim.x) {
        float4 v = ((const float4*)src)[i];
        __half2 h0 = __floats2half2_rn(v.x, v.y);
        __half2 h1 = __floats2half2_rn(v.z, v.w);
        ((__half2*)dst)[2 * i]     = h0;
        ((__half2*)dst)[2 * i + 1] = h1;
    }
}

// ---------------------------------------------------------------------------
// fp16 HMMA GEMM (unified, ldmatrix frags): C = A[M,384] @ W[384,384]^T + bias
// A, W row-major fp16. 128x128 tile, BK=32 (2 ksteps of 16), 8 warps
// (4 M x 2 N), warp tile 32x64, 2-stage cp.async, 40KB smem, 2 CTAs/SM.
// ---------------------------------------------------------------------------
#define HS      40
#define TILE_H  (128 * HS)            // 5120 halves per array per stage
#define GEMM_SMEM_H (4 * TILE_H * 2)  // 40960 B

__global__ __launch_bounds__(256, 2)
void gemm_h_kernel(const __half* __restrict__ A,
                   const __half* __restrict__ W,
                   const float* __restrict__ bias,
                   float* __restrict__ C)
{
    extern __shared__ __half smh[];
    __half* AsBuf = smh;                   // 2 stages
    __half* BsBuf = smh + 2 * TILE_H;      // 2 stages

    const int tid  = threadIdx.x;
    const int wid  = tid >> 5;
    const int lane = tid & 31;
    const int g = lane >> 2;
    const int t = lane & 3;
    const int wm = wid >> 1;
    const int wn = wid & 1;

    const int m0 = blockIdx.y * 128;
    const int n0 = blockIdx.x * 128;

    const uint32_t sAu = smem_u32(AsBuf);
    const uint32_t sBu = smem_u32(BsBuf);

    // ldmatrix per-lane address offsets (bytes within a stage)
    // A, per mt: 16 rows (lane&15) at base wm*32+mt*16; k-half sel lane>>4
    uint32_t offA[2];
#pragma unroll
    for (int mt = 0; mt < 2; mt++) {
        int row = wm * 32 + mt * 16 + (lane & 15);
        int kof = ((lane >> 4) & 1) * 8;
        offA[mt] = (uint32_t)(row * HS + kof) * 2;
    }
    // B, per nt-pair p: rows n = wn*64 + (2p + (lane>>4))*8 + (lane&7),
    // k-half sel (lane>>3)&1
    uint32_t offB[4];
#pragma unroll
    for (int p = 0; p < 4; p++) {
        int n = wn * 64 + (2 * p + ((lane >> 4) & 1)) * 8 + (lane & 7);
        int kof = ((lane >> 3) & 1) * 8;
        offB[p] = (uint32_t)(n * HS + kof) * 2;
    }

    float acc[2][8][4];
#pragma unroll
    for (int mt = 0; mt < 2; mt++)
#pragma unroll
        for (int nt = 0; nt < 8; nt++)
#pragma unroll
            for (int q = 0; q < 4; q++) acc[mt][nt][q] = 0.f;

    auto load_tile = [&](int kt, int buf) {
        const int k0 = kt * 32;
#pragma unroll
        for (int it = 0; it < 2; it++) {
            int idx = it * 256 + tid;
            int r = idx >> 2, c = idx & 3;
            cp16(sBu + (uint32_t)(buf * TILE_H + r * HS + c * 8) * 2,
                 &W[(size_t)(n0 + r) * DIM + k0 + c * 8]);
        }
#pragma unroll
        for (int it = 0; it < 2; it++) {
            int idx = it * 256 + tid;
            int r = idx >> 2, c = idx & 3;
            cp16(sAu + (uint32_t)(buf * TILE_H + r * HS + c * 8) * 2,
                 &A[(size_t)(m0 + r) * DIM + k0 + c * 8]);
        }
        CP_COMMIT();
    };

    load_tile(0, 0);

    for (int kt = 0; kt < 12; kt++) {
        if (kt + 1 < 12) {
            load_tile(kt + 1, (kt + 1) & 1);
            CP_WAIT1();
        } else {
            CP_WAIT0();
        }
        __syncthreads();

        const int buf = kt & 1;
        const uint32_t stA = sAu + (uint32_t)(buf * TILE_H) * 2;
        const uint32_t stB = sBu + (uint32_t)(buf * TILE_H) * 2;

#pragma unroll
        for (int s = 0; s < 2; s++) {
            const uint32_t kbb = (uint32_t)(s * 16) * 2;   // byte offset
            uint32_t bf[8][2];
#pragma unroll
            for (int p = 0; p < 4; p++) {
                uint32_t r0, r1, r2, r3;
                ldsm_x4(r0, r1, r2, r3, stB + offB[p] + kbb);
                bf[2 * p][0] = r0;     bf[2 * p][1] = r1;
                bf[2 * p + 1][0] = r2; bf[2 * p + 1][1] = r3;
            }
#pragma unroll
            for (int mt = 0; mt < 2; mt++) {
                uint32_t af[4];
                ldsm_x4(af[0], af[1], af[2], af[3], stA + offA[mt] + kbb);
#pragma unroll
                for (int nt = 0; nt < 8; nt++)
                    mma_f16(acc[mt][nt], af, bf[nt]);
            }
        }
        __syncthreads();
    }

#pragma unroll
    for (int mt = 0; mt < 2; mt++) {
        int row = m0 + wm * 32 + mt * 16 + g;
#pragma unroll
        for (int nt = 0; nt < 8; nt++) {
            int col = n0 + wn * 64 + nt * 8 + t * 2;
            float b0 = bias[col], b1 = bias[col + 1];
            float2 v0 = make_float2(acc[mt][nt][0] + b0, acc[mt][nt][1] + b1);
            float2 v1 = make_float2(acc[mt][nt][2] + b0, acc[mt][nt][3] + b1);
            *(float2*)&C[(size_t)row * DIM + col] = v0;
            *(float2*)&C[(size_t)(row + 8) * DIM + col] = v1;
        }
    }
}

// ---------------------------------------------------------------------------
// Grouped conv (k=3, SAME, groups=192, 2 in-ch per group) + SiLU  (R13 exact)
// ---------------------------------------------------------------------------
__global__ __launch_bounds__(1024)
void conv_silu_kernel(const float* __restrict__ conv_w,
                      const float* __restrict__ conv_b)
{
    __shared__ float s[34][65];
    const int b  = blockIdx.z;
    const int d0 = blockIdx.y * 32;
    const int l0 = blockIdx.x * 32;
    const int tid = threadIdx.y * 32 + threadIdx.x;

    for (int e = tid; e < 34 * 64; e += 1024) {
        int li = e >> 6;
        int ci = e & 63;
        int l = l0 - 1 + li;
        float v = 0.f;
        if (l >= 0 && l < LEN)
            v = g_xp[(b * LEN + l) * DIM + 2 * d0 + ci];
        s[li][ci] = v;
    }
    __syncthreads();

    const int tx = threadIdx.x, ty = threadIdx.y;
    const int d = d0 + ty;
    float acc = conv_b[d];
    const float* w = conv_w + d * 6;
#pragma unroll
    for (int i = 0; i < 2; i++)
#pragma unroll
        for (int j = 0; j < 3; j++)
            acc = fmaf(s[tx + j][2 * ty + i], w[i * 3 + j], acc);
    float y = acc / (1.f + __expf(-acc));
    g_xc[(b * DIN + d) * LEN + l0 + tx] = y;
}

// ---------------------------------------------------------------------------
// x_proj (R13 exact)
// ---------------------------------------------------------------------------
__global__ __launch_bounds__(128)
void xproj_kernel(const float* __restrict__ x_proj_w)
{
    __shared__ float sW[14 * DIN];
    const int b = blockIdx.y;
    const int l = blockIdx.x * 128 + threadIdx.x;
    const int r0 = blockIdx.z * 14;

    for (int i = threadIdx.x; i < 14 * DIN; i += 128)
        sW[i] = x_proj_w[r0 * DIN + i];
    __syncthreads();

    float acc[14];
#pragma unroll
    for (int j = 0; j < 14; j++) acc[j] = 0.f;

    for (int d = 0; d < DIN; d++) {
        float v = g_xc[(b * DIN + d) * LEN + l];
#pragma unroll
        for (int j = 0; j < 14; j++)
            acc[j] = fmaf(sW[j * DIN + d], v, acc[j]);
    }
#pragma unroll
    for (int j = 0; j < 14; j++) {
        int r = r0 + j;
        if (r < DTRANK)
            g_dt[(b * DTRANK + r) * LEN + l] = acc[j];
        else if (r < DTRANK + DSTATE)
            g_Bm[(b * LEN + l) * DSTATE + (r - DTRANK)] = acc[j];
        else
            g_Cm[(b * LEN + l) * DSTATE + (r - DTRANK - DSTATE)] = acc[j];
    }
}

// ---------------------------------------------------------------------------
// delta (R13 exact)
// ---------------------------------------------------------------------------
__global__ __launch_bounds__(128)
void delta_kernel(const float* __restrict__ dt_proj_w,
                  const float* __restrict__ dt_proj_b)
{
    __shared__ float sW[24 * DTRANK];
    const int b = blockIdx.y;
    const int l = blockIdx.x * 128 + threadIdx.x;
    const int d0 = blockIdx.z * 24;

    for (int i = threadIdx.x; i < 24 * DTRANK; i += 128)
        sW[i] = dt_proj_w[d0 * DTRANK + i];
    __syncthreads();

    float dt[DTRANK];
#pragma unroll
    for (int r = 0; r < DTRANK; r++)
        dt[r] = g_dt[(b * DTRANK + r) * LEN + l];

#pragma unroll 4
    for (int j = 0; j < 24; j++) {
        int d = d0 + j;
        float a = dt_proj_b[d];
#pragma unroll
        for (int r = 0; r < DTRANK; r++)
            a = fmaf(sW[j * DTRANK + r], dt[r], a);
        float sp = (a > 20.f) ? a : log1pf(__expf(a));
        g_delta[(b * DIN + d) * LEN + l] = sp;
    }
}

// ---------------------------------------------------------------------------
// Bidirectional selective scan v2.3 (R13 exact — smem-transpose reduction)
// ---------------------------------------------------------------------------
#define SCHUNK   64
#define SC_BUF   6272
#define SC_DU    4096
#define PB_D     272
#define PB_DIR   (8 * PB_D)
#define SC_SMEM  ((2 * SC_BUF + 2 * PB_DIR) * 4)   // 67584 B

__global__ __launch_bounds__(256)
void scan_kernel(const float* __restrict__ A_log,
                 const float* __restrict__ Ab_log)
{
    extern __shared__ float ss[];
    float* pbuf = ss + 2 * SC_BUF;
    const int b  = blockIdx.x / (DIN / 8);
    const int d0 = (blockIdx.x % (DIN / 8)) * 8;
    const int tid = threadIdx.x;
    const int wid = tid >> 5, lane = tid & 31;
    const bool bwd = wid >= 4;
    const int w = bwd ? wid - 4 : wid;
    const int half = lane >> 4, n = lane & 15;
    const int dloc = 2 * w + half;
    const int dg = d0 + dloc;

    const float Aval = -__expf(bwd ? Ab_log[dg * DSTATE + n]
                                   : A_log[dg * DSTATE + n]);
    float* pst = pbuf + (bwd ? PB_DIR : 0) + dloc * PB_D + n * 17;

    const int rdir = tid >> 7;
    const int rrem = tid & 127;
    const int rd   = rrem >> 4;
    const int rt   = rrem & 15;
    const float* rq = pbuf + rdir * PB_DIR + rd * PB_D + rt;
    float* ybase = (rdir ? g_yb : g_yf) + (size_t)(b * DIN + d0 + rd) * LEN;

    const uint32_t sbase = smem_u32(ss);

    auto load_chunk = [&](int c, int buf) {
        const uint32_t dstb = sbase + (uint32_t)buf * SC_BUF * 4;
        const int lf = c * SCHUNK;
        const int lb = LEN - (c + 1) * SCHUNK;
#pragma unroll
        for (int it = 0; it < 4; it++) {
            int task = it * 256 + tid;
            int arr = task >> 8, r = task & 255;
            int lo = r >> 2, n4 = (r & 3) * 4;
            int ls = (arr < 2) ? lf + lo : lb + lo;
            const float* src = ((arr & 1) ? g_Cm : g_Bm)
                + ((size_t)(b * LEN + ls) * DSTATE + n4);
            cp16(dstb + (uint32_t)(arr * 1024 + lo * 16 + n4) * 4, src);
        }
#pragma unroll
        for (int it = 0; it < 2; it++) {
            int q = it * 256 + tid;
            int arr = q >> 7, s = q & 127;
            int dl = s >> 4, l4 = (s & 15) * 4;
            int ls = (arr < 2) ? lf + l4 : lb + l4;
            const float* src = ((arr & 1) ? g_xc : g_delta)
                + ((size_t)(b * DIN + d0 + dl) * LEN + ls);
            cp16(dstb + (uint32_t)(SC_DU + arr * 544 + dl * 68 + l4) * 4, src);
        }
    };

    float h = 0.f;
    load_chunk(0, 0);
    CP_COMMIT();

    for (int c = 0; c < LEN / SCHUNK; c++) {
        const int buf = c & 1;
        if (c + 1 < LEN / SCHUNK) load_chunk(c + 1, buf ^ 1);
        CP_COMMIT();
        CP_WAIT1();
        __syncthreads();

        const float* sm   = ss + buf * SC_BUF;
        const float* sB   = sm + (bwd ? 2048 : 0);
        const float* sC   = sB + 1024;
        const float* sdel = sm + SC_DU + (bwd ? 1088 : 0) + dloc * 68;
        const float* su   = sdel + 544;

#pragma unroll
        for (int w2 = 0; w2 < 4; w2++) {
            if (!bwd) {
#pragma unroll
                for (int j = 0; j < 4; j++) {
                    const int t0 = (w2 * 4 + j) * 4;
#pragma unroll
                    for (int k = 0; k < 4; k++) {
                        int t = t0 + k;
                        float del = sdel[t], u = su[t];
                        float Bv = sB[t * 16 + n], Cv = sC[t * 16 + n];
                        float dA = __expf(del * Aval);
                        h = fmaf(dA, h, del * u * Bv);
                        pst[j * 4 + k] = h * Cv;
                    }
                }
            } else {
#pragma unroll
                for (int j = 0; j < 4; j++) {
                    const int t0 = (15 - (w2 * 4 + j)) * 4;
#pragma unroll
                    for (int k = 0; k < 4; k++) {
                        int t = t0 + 3 - k;
                        float del = sdel[t], u = su[t];
                        float Bv = sB[t * 16 + n], Cv = sC[t * 16 + n];
                        float dA = __expf(del * Aval);
                        h = fmaf(dA, h, del * u * Bv);
                        pst[(3 - j) * 4 + (3 - k)] = h * Cv;
                    }
                }
            }
            __syncthreads();
            {
                float s0 = 0.f, s1 = 0.f;
#pragma unroll
                for (int nn = 0; nn < 16; nn += 2) {
                    s0 += rq[nn * 17];
                    s1 += rq[(nn + 1) * 17];
                }
                int l = (rdir == 0)
                    ? (c * SCHUNK + w2 * 16 + rt)
                    : (LEN - (c + 1) * SCHUNK + (3 - w2) * 16 + rt);
                ybase[l] = s0 + s1;
            }
            __syncthreads();
        }
    }
}

// ---------------------------------------------------------------------------
// fuse_T (R13 exact): transpose + add + fp16 pack -> g_Ah [m][384]
// ---------------------------------------------------------------------------
__global__ __launch_bounds__(1024)
void fuse_T_kernel(const float* __restrict__ Dv)
{
    __shared__ float sy[32][33];
    __shared__ float sz[32][33];
    const int b  = blockIdx.z;
    const int d0 = blockIdx.y * 32;
    const int l0 = blockIdx.x * 32;
    const int tx = threadIdx.x, ty = threadIdx.y;

    const int d = d0 + ty;
    const size_t off = (size_t)(b * DIN + d) * LEN + l0 + tx;
    float yf = g_yf[off];
    float yb = g_yb[off];
    float xc = g_xc[off];
    sy[ty][tx] = yf + yb + 2.f * Dv[d] * xc;
    sz[ty][tx] = xc;
    __syncthreads();

    __half* dst = g_Ah + (size_t)(b * LEN + l0 + ty) * DIM;
    dst[d0 + tx]       = __float2half_rn(sy[tx][ty]);
    dst[DIN + d0 + tx] = __float2half_rn(sz[tx][ty]);
}

// ---------------------------------------------------------------------------
// Launch
// ---------------------------------------------------------------------------
extern "C" void kernel_launch(void* const* d_in, const int* in_sizes, int n_in,
                              void* d_out, int out_size)
{
    (void)in_sizes; (void)n_in; (void)out_size;
    const float* x          = (const float*)d_in[0];
    const float* in_proj_w  = (const float*)d_in[1];
    const float* in_proj_b  = (const float*)d_in[2];
    const float* conv_w     = (const float*)d_in[3];
    const float* conv_b     = (const float*)d_in[4];
    const float* A_log      = (const float*)d_in[5];
    const float* Ab_log     = (const float*)d_in[6];
    const float* Dv         = (const float*)d_in[7];
    const float* x_proj_w   = (const float*)d_in[8];
    const float* dt_proj_w  = (const float*)d_in[9];
    const float* dt_proj_b  = (const float*)d_in[10];
    const float* out_proj_w = (const float*)d_in[11];
    const float* out_proj_b = (const float*)d_in[12];
    float* out = (float*)d_out;

    float* xp_ptr;
    __half *xh_ptr, *ah_ptr, *wih_ptr, *woh_ptr;
    cudaGetSymbolAddress((void**)&xp_ptr, g_xp);
    cudaGetSymbolAddress((void**)&xh_ptr, g_xh);
    cudaGetSymbolAddress((void**)&ah_ptr, g_Ah);
    cudaGetSymbolAddress((void**)&wih_ptr, g_wih);
    cudaGetSymbolAddress((void**)&woh_ptr, g_woh);

    cudaFuncSetAttribute(scan_kernel,
                         cudaFuncAttributeMaxDynamicSharedMemorySize, SC_SMEM);

    // 1-3. fp16 pre-conversion
    cvt_half<<<144, 256>>>(in_proj_w, wih_ptr, DIM * DIM / 4);
    cvt_half<<<144, 256>>>(out_proj_w, woh_ptr, DIM * DIM / 4);
    cvt_half<<<1024, 256>>>(x, xh_ptr, MTOT * DIM / 4);

    // 4. in_proj GEMM (fp16 HMMA + ldmatrix)  [profiled slot]
    gemm_h_kernel<<<dim3(DIM / 128, MTOT / 128), 256, GEMM_SMEM_H>>>(
        xh_ptr, wih_ptr, in_proj_b, xp_ptr);

    // 5. conv + silu -> g_xc
    conv_silu_kernel<<<dim3(LEN / 32, DIN / 32, NB), dim3(32, 32)>>>(
        conv_w, conv_b);

    // 6. x_proj split -> g_dt, g_Bm, g_Cm
    xproj_kernel<<<dim3(LEN / 128, NB, 4), 128>>>(x_proj_w);

    // 7. delta = softplus(dt_proj) -> g_delta
    delta_kernel<<<dim3(LEN / 128, NB, 8), 128>>>(dt_proj_w, dt_proj_b);

    // 8. bidirectional scan v2.3 -> g_yf, g_yb
    scan_kernel<<<NB * (DIN / 8), 256, SC_SMEM>>>(A_log, Ab_log);

    // 9. fuse + transpose -> g_Ah (fp16 [m][384])
    fuse_T_kernel<<<dim3(LEN / 32, DIN / 32, NB), dim3(32, 32)>>>(Dv);

    // 10. out_proj GEMM (fp16 HMMA + ldmatrix) -> d_out
    gemm_h_kernel<<<dim3(DIM / 128, MTOT / 128), 256, GEMM_SMEM_H>>>(
        ah_ptr, woh_ptr, out_proj_b, out);
}

// round 16
// speedup vs baseline: 1.0304x; 1.0050x over previous
#include <cuda_runtime.h>
#include <cuda_fp16.h>
#include <cstdint>

// Problem constants
#define BATCH   4
#define SEQ     6144
#define DIM     384
#define FCHUNK  3
#define NB      12      // BATCH*FCHUNK
#define LEN     2048    // SEQ/FCHUNK
#define DIN     192     // DIM/2
#define DSTATE  16
#define DTRANK  24
#define MTOT    (NB*LEN)    // 24576

// ---------------------------------------------------------------------------
// Scratch (static __device__ arrays; no allocation allowed)
// ---------------------------------------------------------------------------
__device__ float  g_xp[MTOT * DIM];           // in_proj output (fp32)
__device__ float  g_xc[NB * DIN * LEN];       // (b,d,l) conv+silu output
__device__ float  g_dt[NB * DTRANK * LEN];    // (b,r,l)
__device__ float  g_Bm[NB * LEN * DSTATE];    // (b,l,n)
__device__ float  g_Cm[NB * LEN * DSTATE];    // (b,l,n)
__device__ float  g_delta[NB * DIN * LEN];    // (b,d,l)
__device__ float  g_yf[NB * DIN * LEN];       // fwd scan out (b,d,l)
__device__ float  g_yb[NB * DIN * LEN];       // bwd scan out (b,d,l)
__device__ __half g_xh[MTOT * DIM];           // fp16 x
__device__ __half g_Ah[MTOT * DIM];           // fp16 [ysum | xc], row-major
__device__ __half g_wih[DIM * DIM];           // fp16 in_proj_w
__device__ __half g_woh[DIM * DIM];           // fp16 out_proj_w

// ---------------------------------------------------------------------------
// helpers
// ---------------------------------------------------------------------------
__device__ __forceinline__ uint32_t smem_u32(const void* p) {
    uint32_t a;
    asm("{ .reg .u64 t; cvta.to.shared.u64 t, %1; cvt.u32.u64 %0, t; }"
        : "=r"(a) : "l"(p));
    return a;
}
__device__ __forceinline__ void cp16(uint32_t dst, const void* src) {
    asm volatile("cp.async.ca.shared.global [%0], [%1], 16;"
                 :: "r"(dst), "l"(src) : "memory");
}
#define CP_COMMIT() asm volatile("cp.async.commit_group;" ::: "memory")
#define CP_WAIT1()  asm volatile("cp.async.wait_group 1;" ::: "memory")
#define CP_WAIT0()  asm volatile("cp.async.wait_group 0;" ::: "memory")

__device__ __forceinline__ void mma_f16(float* c, const uint32_t* a,
                                        const uint32_t* b) {
    asm volatile(
        "mma.sync.aligned.m16n8k16.row.col.f32.f16.f16.f32 "
        "{%0,%1,%2,%3}, {%4,%5,%6,%7}, {%8,%9}, {%0,%1,%2,%3};"
        : "+f"(c[0]), "+f"(c[1]), "+f"(c[2]), "+f"(c[3])
        : "r"(a[0]), "r"(a[1]), "r"(a[2]), "r"(a[3]), "r"(b[0]), "r"(b[1]));
}
__device__ __forceinline__ void ldsm_x4(uint32_t& r0, uint32_t& r1,
                                        uint32_t& r2, uint32_t& r3,
                                        uint32_t addr) {
    asm volatile("ldmatrix.sync.aligned.m8n8.x4.shared.b16 {%0,%1,%2,%3}, [%4];"
                 : "=r"(r0), "=r"(r1), "=r"(r2), "=r"(r3) : "r"(addr));
}

// ---------------------------------------------------------------------------
// cvt_half: fp32 -> fp16, float4-granular grid-stride
// ---------------------------------------------------------------------------
__global__ __launch_bounds__(256)
void cvt_half(const float* __restrict__ src, __half* __restrict__ dst, int n4)
{
    for (int i = blockIdx.x * blockDim.x + threadIdx.x; i < n4;
         i += gridDim.x * blockDim.x) {
        float4 v = ((const float4*)src)[i];
        __half2 h0 = __floats2half2_rn(v.x, v.y);
        __half2 h1 = __floats2half2_rn(v.z, v.w);
        ((__half2*)dst)[2 * i]     = h0;
        ((__half2*)dst)[2 * i + 1] = h1;
    }
}

// ---------------------------------------------------------------------------
// fp16 HMMA GEMM (64x128 tile, 128 thr / 4 warps, ldmatrix frags):
// C = A[M,384] @ W[384,384]^T + bias. BK=32 (2 ksteps of 16), warp tile
// 32x64 (2M x 2N warps), 2-stage cp.async, 30.7KB smem, 4 CTAs/SM (regs).
// ---------------------------------------------------------------------------
#define HS       40
#define TILE_A   (64 * HS)             // 2560 halves per stage
#define TILE_B   (128 * HS)            // 5120 halves per stage
#define GEMM_SMEM_H ((2 * TILE_A + 2 * TILE_B) * 2)   // 30720 B

__global__ __launch_bounds__(128, 4)
void gemm_h_kernel(const __half* __restrict__ A,
                   const __half* __restrict__ W,
                   const float* __restrict__ bias,
                   float* __restrict__ C)
{
    extern __shared__ __half smh[];
    __half* AsBuf = smh;                   // 2 stages of TILE_A
    __half* BsBuf = smh + 2 * TILE_A;      // 2 stages of TILE_B

    const int tid  = threadIdx.x;
    const int wid  = tid >> 5;
    const int lane = tid & 31;
    const int g = lane >> 2;
    const int t = lane & 3;
    const int wm = wid >> 1;               // 0..1 (M)
    const int wn = wid & 1;                // 0..1 (N)

    const int m0 = blockIdx.y * 64;
    const int n0 = blockIdx.x * 128;

    const uint32_t sAu = smem_u32(AsBuf);
    const uint32_t sBu = smem_u32(BsBuf);

    // ldmatrix per-lane address offsets (bytes within a stage)
    uint32_t offA[2];
#pragma unroll
    for (int mt = 0; mt < 2; mt++) {
        int row = wm * 32 + mt * 16 + (lane & 15);
        int kof = ((lane >> 4) & 1) * 8;
        offA[mt] = (uint32_t)(row * HS + kof) * 2;
    }
    uint32_t offB[4];
#pragma unroll
    for (int p = 0; p < 4; p++) {
        int n = wn * 64 + (2 * p + ((lane >> 4) & 1)) * 8 + (lane & 7);
        int kof = ((lane >> 3) & 1) * 8;
        offB[p] = (uint32_t)(n * HS + kof) * 2;
    }

    float acc[2][8][4];
#pragma unroll
    for (int mt = 0; mt < 2; mt++)
#pragma unroll
        for (int nt = 0; nt < 8; nt++)
#pragma unroll
            for (int q = 0; q < 4; q++) acc[mt][nt][q] = 0.f;

    auto load_tile = [&](int kt, int buf) {
        const int k0 = kt * 32;
        // B: 128 rows x 4 granules = 512 -> 4/thread
#pragma unroll
        for (int it = 0; it < 4; it++) {
            int idx = it * 128 + tid;
            int r = idx >> 2, c = idx & 3;
            cp16(sBu + (uint32_t)(buf * TILE_B + r * HS + c * 8) * 2,
                 &W[(size_t)(n0 + r) * DIM + k0 + c * 8]);
        }
        // A: 64 rows x 4 granules = 256 -> 2/thread
#pragma unroll
        for (int it = 0; it < 2; it++) {
            int idx = it * 128 + tid;
            int r = idx >> 2, c = idx & 3;
            cp16(sAu + (uint32_t)(buf * TILE_A + r * HS + c * 8) * 2,
                 &A[(size_t)(m0 + r) * DIM + k0 + c * 8]);
        }
        CP_COMMIT();
    };

    load_tile(0, 0);

    for (int kt = 0; kt < 12; kt++) {
        if (kt + 1 < 12) {
            load_tile(kt + 1, (kt + 1) & 1);
            CP_WAIT1();
        } else {
            CP_WAIT0();
        }
        __syncthreads();

        const int buf = kt & 1;
        const uint32_t stA = sAu + (uint32_t)(buf * TILE_A) * 2;
        const uint32_t stB = sBu + (uint32_t)(buf * TILE_B) * 2;

#pragma unroll
        for (int s = 0; s < 2; s++) {
            const uint32_t kbb = (uint32_t)(s * 16) * 2;
            uint32_t bf[8][2];
#pragma unroll
            for (int p = 0; p < 4; p++) {
                uint32_t r0, r1, r2, r3;
                ldsm_x4(r0, r1, r2, r3, stB + offB[p] + kbb);
                bf[2 * p][0] = r0;     bf[2 * p][1] = r1;
                bf[2 * p + 1][0] = r2; bf[2 * p + 1][1] = r3;
            }
#pragma unroll
            for (int mt = 0; mt < 2; mt++) {
                uint32_t af[4];
                ldsm_x4(af[0], af[1], af[2], af[3], stA + offA[mt] + kbb);
#pragma unroll
                for (int nt = 0; nt < 8; nt++)
                    mma_f16(acc[mt][nt], af, bf[nt]);
            }
        }
        __syncthreads();
    }

#pragma unroll
    for (int mt = 0; mt < 2; mt++) {
        int row = m0 + wm * 32 + mt * 16 + g;
#pragma unroll
        for (int nt = 0; nt < 8; nt++) {
            int col = n0 + wn * 64 + nt * 8 + t * 2;
            float b0 = bias[col], b1 = bias[col + 1];
            float2 v0 = make_float2(acc[mt][nt][0] + b0, acc[mt][nt][1] + b1);
            float2 v1 = make_float2(acc[mt][nt][2] + b0, acc[mt][nt][3] + b1);
            *(float2*)&C[(size_t)row * DIM + col] = v0;
            *(float2*)&C[(size_t)(row + 8) * DIM + col] = v1;
        }
    }
}

// ---------------------------------------------------------------------------
// Grouped conv (k=3, SAME, groups=192, 2 in-ch per group) + SiLU  (R15 exact)
// ---------------------------------------------------------------------------
__global__ __launch_bounds__(1024)
void conv_silu_kernel(const float* __restrict__ conv_w,
                      const float* __restrict__ conv_b)
{
    __shared__ float s[34][65];
    const int b  = blockIdx.z;
    const int d0 = blockIdx.y * 32;
    const int l0 = blockIdx.x * 32;
    const int tid = threadIdx.y * 32 + threadIdx.x;

    for (int e = tid; e < 34 * 64; e += 1024) {
        int li = e >> 6;
        int ci = e & 63;
        int l = l0 - 1 + li;
        float v = 0.f;
        if (l >= 0 && l < LEN)
            v = g_xp[(b * LEN + l) * DIM + 2 * d0 + ci];
        s[li][ci] = v;
    }
    __syncthreads();

    const int tx = threadIdx.x, ty = threadIdx.y;
    const int d = d0 + ty;
    float acc = conv_b[d];
    const float* w = conv_w + d * 6;
#pragma unroll
    for (int i = 0; i < 2; i++)
#pragma unroll
        for (int j = 0; j < 3; j++)
            acc = fmaf(s[tx + j][2 * ty + i], w[i * 3 + j], acc);
    float y = acc / (1.f + __expf(-acc));
    g_xc[(b * DIN + d) * LEN + l0 + tx] = y;
}

// ---------------------------------------------------------------------------
// x_proj (R15 exact)
// ---------------------------------------------------------------------------
__global__ __launch_bounds__(128)
void xproj_kernel(const float* __restrict__ x_proj_w)
{
    __shared__ float sW[14 * DIN];
    const int b = blockIdx.y;
    const int l = blockIdx.x * 128 + threadIdx.x;
    const int r0 = blockIdx.z * 14;

    for (int i = threadIdx.x; i < 14 * DIN; i += 128)
        sW[i] = x_proj_w[r0 * DIN + i];
    __syncthreads();

    float acc[14];
#pragma unroll
    for (int j = 0; j < 14; j++) acc[j] = 0.f;

    for (int d = 0; d < DIN; d++) {
        float v = g_xc[(b * DIN + d) * LEN + l];
#pragma unroll
        for (int j = 0; j < 14; j++)
            acc[j] = fmaf(sW[j * DIN + d], v, acc[j]);
    }
#pragma unroll
    for (int j = 0; j < 14; j++) {
        int r = r0 + j;
        if (r < DTRANK)
            g_dt[(b * DTRANK + r) * LEN + l] = acc[j];
        else if (r < DTRANK + DSTATE)
            g_Bm[(b * LEN + l) * DSTATE + (r - DTRANK)] = acc[j];
        else
            g_Cm[(b * LEN + l) * DSTATE + (r - DTRANK - DSTATE)] = acc[j];
    }
}

// ---------------------------------------------------------------------------
// delta (R15 exact)
// ---------------------------------------------------------------------------
__global__ __launch_bounds__(128)
void delta_kernel(const float* __restrict__ dt_proj_w,
                  const float* __restrict__ dt_proj_b)
{
    __shared__ float sW[24 * DTRANK];
    const int b = blockIdx.y;
    const int l = blockIdx.x * 128 + threadIdx.x;
    const int d0 = blockIdx.z * 24;

    for (int i = threadIdx.x; i < 24 * DTRANK; i += 128)
        sW[i] = dt_proj_w[d0 * DTRANK + i];
    __syncthreads();

    float dt[DTRANK];
#pragma unroll
    for (int r = 0; r < DTRANK; r++)
        dt[r] = g_dt[(b * DTRANK + r) * LEN + l];

#pragma unroll 4
    for (int j = 0; j < 24; j++) {
        int d = d0 + j;
        float a = dt_proj_b[d];
#pragma unroll
        for (int r = 0; r < DTRANK; r++)
            a = fmaf(sW[j * DTRANK + r], dt[r], a);
        float sp = (a > 20.f) ? a : log1pf(__expf(a));
        g_delta[(b * DIN + d) * LEN + l] = sp;
    }
}

// ---------------------------------------------------------------------------
// Bidirectional selective scan v2.3 (R15 exact — smem-transpose reduction)
// ---------------------------------------------------------------------------
#define SCHUNK   64
#define SC_BUF   6272
#define SC_DU    4096
#define PB_D     272
#define PB_DIR   (8 * PB_D)
#define SC_SMEM  ((2 * SC_BUF + 2 * PB_DIR) * 4)   // 67584 B

__global__ __launch_bounds__(256)
void scan_kernel(const float* __restrict__ A_log,
                 const float* __restrict__ Ab_log)
{
    extern __shared__ float ss[];
    float* pbuf = ss + 2 * SC_BUF;
    const int b  = blockIdx.x / (DIN / 8);
    const int d0 = (blockIdx.x % (DIN / 8)) * 8;
    const int tid = threadIdx.x;
    const int wid = tid >> 5, lane = tid & 31;
    const bool bwd = wid >= 4;
    const int w = bwd ? wid - 4 : wid;
    const int half = lane >> 4, n = lane & 15;
    const int dloc = 2 * w + half;
    const int dg = d0 + dloc;

    const float Aval = -__expf(bwd ? Ab_log[dg * DSTATE + n]
                                   : A_log[dg * DSTATE + n]);
    float* pst = pbuf + (bwd ? PB_DIR : 0) + dloc * PB_D + n * 17;

    const int rdir = tid >> 7;
    const int rrem = tid & 127;
    const int rd   = rrem >> 4;
    const int rt   = rrem & 15;
    const float* rq = pbuf + rdir * PB_DIR + rd * PB_D + rt;
    float* ybase = (rdir ? g_yb : g_yf) + (size_t)(b * DIN + d0 + rd) * LEN;

    const uint32_t sbase = smem_u32(ss);

    auto load_chunk = [&](int c, int buf) {
        const uint32_t dstb = sbase + (uint32_t)buf * SC_BUF * 4;
        const int lf = c * SCHUNK;
        const int lb = LEN - (c + 1) * SCHUNK;
#pragma unroll
        for (int it = 0; it < 4; it++) {
            int task = it * 256 + tid;
            int arr = task >> 8, r = task & 255;
            int lo = r >> 2, n4 = (r & 3) * 4;
            int ls = (arr < 2) ? lf + lo : lb + lo;
            const float* src = ((arr & 1) ? g_Cm : g_Bm)
                + ((size_t)(b * LEN + ls) * DSTATE + n4);
            cp16(dstb + (uint32_t)(arr * 1024 + lo * 16 + n4) * 4, src);
        }
#pragma unroll
        for (int it = 0; it < 2; it++) {
            int q = it * 256 + tid;
            int arr = q >> 7, s = q & 127;
            int dl = s >> 4, l4 = (s & 15) * 4;
            int ls = (arr < 2) ? lf + l4 : lb + l4;
            const float* src = ((arr & 1) ? g_xc : g_delta)
                + ((size_t)(b * DIN + d0 + dl) * LEN + ls);
            cp16(dstb + (uint32_t)(SC_DU + arr * 544 + dl * 68 + l4) * 4, src);
        }
    };

    float h = 0.f;
    load_chunk(0, 0);
    CP_COMMIT();

    for (int c = 0; c < LEN / SCHUNK; c++) {
        const int buf = c & 1;
        if (c + 1 < LEN / SCHUNK) load_chunk(c + 1, buf ^ 1);
        CP_COMMIT();
        CP_WAIT1();
        __syncthreads();

        const float* sm   = ss + buf * SC_BUF;
        const float* sB   = sm + (bwd ? 2048 : 0);
        const float* sC   = sB + 1024;
        const float* sdel = sm + SC_DU + (bwd ? 1088 : 0) + dloc * 68;
        const float* su   = sdel + 544;

#pragma unroll
        for (int w2 = 0; w2 < 4; w2++) {
            if (!bwd) {
#pragma unroll
                for (int j = 0; j < 4; j++) {
                    const int t0 = (w2 * 4 + j) * 4;
#pragma unroll
                    for (int k = 0; k < 4; k++) {
                        int t = t0 + k;
                        float del = sdel[t], u = su[t];
                        float Bv = sB[t * 16 + n], Cv = sC[t * 16 + n];
                        float dA = __expf(del * Aval);
                        h = fmaf(dA, h, del * u * Bv);
                        pst[j * 4 + k] = h * Cv;
                    }
                }
            } else {
#pragma unroll
                for (int j = 0; j < 4; j++) {
                    const int t0 = (15 - (w2 * 4 + j)) * 4;
#pragma unroll
                    for (int k = 0; k < 4; k++) {
                        int t = t0 + 3 - k;
                        float del = sdel[t], u = su[t];
                        float Bv = sB[t * 16 + n], Cv = sC[t * 16 + n];
                        float dA = __expf(del * Aval);
                        h = fmaf(dA, h, del * u * Bv);
                        pst[(3 - j) * 4 + (3 - k)] = h * Cv;
                    }
                }
            }
            __syncthreads();
            {
                float s0 = 0.f, s1 = 0.f;
#pragma unroll
                for (int nn = 0; nn < 16; nn += 2) {
                    s0 += rq[nn * 17];
                    s1 += rq[(nn + 1) * 17];
                }
                int l = (rdir == 0)
                    ? (c * SCHUNK + w2 * 16 + rt)
                    : (LEN - (c + 1) * SCHUNK + (3 - w2) * 16 + rt);
                ybase[l] = s0 + s1;
            }
            __syncthreads();
        }
    }
}

// ---------------------------------------------------------------------------
// fuse_T (R15 exact): transpose + add + fp16 pack -> g_Ah [m][384]
// ---------------------------------------------------------------------------
__global__ __launch_bounds__(1024)
void fuse_T_kernel(const float* __restrict__ Dv)
{
    __shared__ float sy[32][33];
    __shared__ float sz[32][33];
    const int b  = blockIdx.z;
    const int d0 = blockIdx.y * 32;
    const int l0 = blockIdx.x * 32;
    const int tx = threadIdx.x, ty = threadIdx.y;

    const int d = d0 + ty;
    const size_t off = (size_t)(b * DIN + d) * LEN + l0 + tx;
    float yf = g_yf[off];
    float yb = g_yb[off];
    float xc = g_xc[off];
    sy[ty][tx] = yf + yb + 2.f * Dv[d] * xc;
    sz[ty][tx] = xc;
    __syncthreads();

    __half* dst = g_Ah + (size_t)(b * LEN + l0 + ty) * DIM;
    dst[d0 + tx]       = __float2half_rn(sy[tx][ty]);
    dst[DIN + d0 + tx] = __float2half_rn(sz[tx][ty]);
}

// ---------------------------------------------------------------------------
// Launch
// ---------------------------------------------------------------------------
extern "C" void kernel_launch(void* const* d_in, const int* in_sizes, int n_in,
                              void* d_out, int out_size)
{
    (void)in_sizes; (void)n_in; (void)out_size;
    const float* x          = (const float*)d_in[0];
    const float* in_proj_w  = (const float*)d_in[1];
    const float* in_proj_b  = (const float*)d_in[2];
    const float* conv_w     = (const float*)d_in[3];
    const float* conv_b     = (const float*)d_in[4];
    const float* A_log      = (const float*)d_in[5];
    const float* Ab_log     = (const float*)d_in[6];
    const float* Dv         = (const float*)d_in[7];
    const float* x_proj_w   = (const float*)d_in[8];
    const float* dt_proj_w  = (const float*)d_in[9];
    const float* dt_proj_b  = (const float*)d_in[10];
    const float* out_proj_w = (const float*)d_in[11];
    const float* out_proj_b = (const float*)d_in[12];
    float* out = (float*)d_out;

    float* xp_ptr;
    __half *xh_ptr, *ah_ptr, *wih_ptr, *woh_ptr;
    cudaGetSymbolAddress((void**)&xp_ptr, g_xp);
    cudaGetSymbolAddress((void**)&xh_ptr, g_xh);
    cudaGetSymbolAddress((void**)&ah_ptr, g_Ah);
    cudaGetSymbolAddress((void**)&wih_ptr, g_wih);
    cudaGetSymbolAddress((void**)&woh_ptr, g_woh);

    cudaFuncSetAttribute(scan_kernel,
                         cudaFuncAttributeMaxDynamicSharedMemorySize, SC_SMEM);

    // 1-3. fp16 pre-conversion
    cvt_half<<<144, 256>>>(in_proj_w, wih_ptr, DIM * DIM / 4);
    cvt_half<<<144, 256>>>(out_proj_w, woh_ptr, DIM * DIM / 4);
    cvt_half<<<1024, 256>>>(x, xh_ptr, MTOT * DIM / 4);

    // 4. in_proj GEMM (fp16 HMMA, 64x128 tiles, 4 CTA/SM)  [profiled slot]
    gemm_h_kernel<<<dim3(DIM / 128, MTOT / 64), 128, GEMM_SMEM_H>>>(
        xh_ptr, wih_ptr, in_proj_b, xp_ptr);

    // 5. conv + silu -> g_xc
    conv_silu_kernel<<<dim3(LEN / 32, DIN / 32, NB), dim3(32, 32)>>>(
        conv_w, conv_b);

    // 6. x_proj split -> g_dt, g_Bm, g_Cm
    xproj_kernel<<<dim3(LEN / 128, NB, 4), 128>>>(x_proj_w);

    // 7. delta = softplus(dt_proj) -> g_delta
    delta_kernel<<<dim3(LEN / 128, NB, 8), 128>>>(dt_proj_w, dt_proj_b);

    // 8. bidirectional scan v2.3 -> g_yf, g_yb
    scan_kernel<<<NB * (DIN / 8), 256, SC_SMEM>>>(A_log, Ab_log);

    // 9. fuse + transpose -> g_Ah (fp16 [m][384])
    fuse_T_kernel<<<dim3(LEN / 32, DIN / 32, NB), dim3(32, 32)>>>(Dv);

    // 10. out_proj GEMM (fp16 HMMA, 64x128 tiles) -> d_out
    gemm_h_kernel<<<dim3(DIM / 128, MTOT / 64), 128, GEMM_SMEM_H>>>(
        ah_ptr, woh_ptr, out_proj_b, out);
}